// round 15
// baseline (speedup 1.0000x reference)
#include <cuda_runtime.h>
#include <float.h>
#include <stdint.h>

#define BATCH 32
#define HH 1024
#define WW 1024
#define TOPK 200
#define HOT_T 0.99966f
#define STRIPS 8          // 8 strips x 128 cols
#define CPW 128           // columns per warp
#define WPB 4             // warps per block
#define RPB 64            // rows per band
#define NBAND (HH / RPB)  // 16
#define SEGS_PER_IMG (STRIPS * NBAND)   // 128
#define SEGCAP 1024
#define PIPE 8            // rows in flight
#define RING 12           // smem ring rows (PIPE + 4)
#define QUADS 34          // 136 cols = 128 + 4 halo each side
#define BLKS_PER_IMG (NBAND * STRIPS / WPB)   // 32
#define SORTN 512

// static device scratch — per-warp private segments (hot front, cold back)
__device__ unsigned long long d_seg[BATCH * SEGS_PER_IMG * SEGCAP];  // 32 MB
__device__ unsigned int d_segcnt[BATCH * SEGS_PER_IMG];              // hot | cold<<16
__device__ int d_imgdone[BATCH];                                     // tickets (self-resetting)

__device__ __forceinline__ float4 mk4(float x) { return make_float4(x, x, x, x); }

#define CP_ASYNC16(saddr, gptr)                                                \
    asm volatile("cp.async.cg.shared.global [%0], [%1], 16;\n"                 \
                 :: "r"(saddr), "l"(gptr) : "memory")
#define CP_COMMIT() asm volatile("cp.async.commit_group;\n" ::: "memory")
#define CP_WAIT7()  asm volatile("cp.async.wait_group 7;\n" ::: "memory")

// Fused kernel: cp.async-pipelined 7x7 max-pool NMS (R11 structure) +
// tail-block per-image top-k. The last block to finish an image (per-image
// ticket) gathers hot keys (> HOT_T) from segment fronts, bitonic-sorts 512
// in the reused smem ring, and writes that image's output. Fallback: 128-
// thread radix select over all segment entries (off-distribution only).
__global__ void __launch_bounds__(128) nms_kernel(const float* __restrict__ in,
                                                  float* __restrict__ out) {
    __shared__ float4 ring[WPB][RING][QUADS];    // 26112 B, reused by tail topk
    __shared__ int s_last;
    __shared__ int s_wsum[4];
    __shared__ int s_cnt;
    __shared__ unsigned s_above, s_digit, s_total;

    const int img = blockIdx.z;
    const int wid = threadIdx.x >> 5;
    const int lane = threadIdx.x & 31;
    const int strip = blockIdx.x * WPB + wid;    // 0..7
    const int band = blockIdx.y;                 // 0..15
    const int out0 = strip * CPW;
    const int colbase = out0 + 4 * lane;
    const int ry0 = band * RPB;
    const int b0 = ry0 - 3;
    const float* base = in + (size_t)img * HH * WW;

    const int segid = (img * NBAND + band) * STRIPS + strip;
    unsigned long long* seg = d_seg + (size_t)segid * SEGCAP;
    int nhot = 0, ncold = 0;

    // clamped source columns for this lane's quads
    int c0 = out0 - 4 + 4 * lane;                // quads 0..31
    c0 = min(max(c0, 0), WW - 4);
    int c1 = out0 + 124 + 4 * lane;              // quads 32,33 (lanes 0,1)
    c1 = min(c1, WW - 4);
    const bool lane2 = lane < 2;

    const uint32_t sbase =
        (uint32_t)__cvta_generic_to_shared(&ring[wid][0][0]);

    // prologue: issue rows 0..PIPE-1 into slots 0..PIPE-1
    #pragma unroll
    for (int i = 0; i < PIPE; i++) {
        int rr = min(max(b0 + i, 0), HH - 1);
        const float* rowp = base + (size_t)rr * WW;
        uint32_t s = sbase + (uint32_t)(i * QUADS * 16);
        CP_ASYNC16(s + lane * 16, rowp + c0);
        if (lane2) CP_ASYNC16(s + (32 + lane) * 16, rowp + c1);
        CP_COMMIT();
    }

    // rolling vertical state: h[r-1..r-3], m3 centered r-2..r-5
    float4 hp0 = mk4(-FLT_MAX), hp1 = hp0, hp2 = hp0;
    float4 m30 = hp0, m31 = hp0, m32 = hp0, m33 = hp0;

    for (int o = 0; o < 6; o++) {                // 72 rows (last 2 junk, guarded)
        #pragma unroll
        for (int j = 0; j < RING; j++) {
            const int i = o * RING + j;
            const int r = b0 + i;
            CP_WAIT7();
            __syncwarp();

            const float4* rb = &ring[wid][j][0];
            float4 L = rb[lane];
            float4 O = rb[lane + 1];
            float4 R = rb[lane + 2];

            // horizontal 7-max from L/O/R quads
            float p3 = fmaxf(fmaxf(O.x, O.y), fmaxf(O.z, O.w));
            float Lzw = fmaxf(L.z, L.w);
            float Ls3 = fmaxf(L.y, Lzw);
            float Rxy = fmaxf(R.x, R.y);
            float4 h;
            h.x = fmaxf(Ls3, p3);
            h.y = fmaxf(Lzw, fmaxf(p3, R.x));
            h.z = fmaxf(L.w, fmaxf(p3, Rxy));
            h.w = fmaxf(p3, fmaxf(Rxy, R.z));

            // vertical cascade
            float4 m3n, pooled;
            m3n.x = fmaxf(fmaxf(hp1.x, hp0.x), h.x);
            m3n.y = fmaxf(fmaxf(hp1.y, hp0.y), h.y);
            m3n.z = fmaxf(fmaxf(hp1.z, hp0.z), h.z);
            m3n.w = fmaxf(fmaxf(hp1.w, hp0.w), h.w);
            pooled.x = fmaxf(fmaxf(m33.x, hp2.x), m3n.x);
            pooled.y = fmaxf(fmaxf(m33.y, hp2.y), m3n.y);
            pooled.z = fmaxf(fmaxf(m33.z, hp2.z), m3n.z);
            pooled.w = fmaxf(fmaxf(m33.w, hp2.w), m3n.w);

            if (r >= ry0 + 3 && r <= ry0 + RPB + 2) {
                // center row r-3 from the ring (own quad)
                const int jc = (j >= 3) ? (j - 3) : (j + 9);
                float4 cv = ring[wid][jc][lane + 1];

                bool pk0 = (cv.x > 0.1f) && (pooled.x == cv.x);
                bool pk1 = (cv.y > 0.1f) && (pooled.y == cv.y);
                bool pk2 = (cv.z > 0.1f) && (pooled.z == cv.z);
                bool pk3 = (cv.w > 0.1f) && (pooled.w == cv.w);
                int pcnt = (int)pk0 + (int)pk1 + (int)pk2 + (int)pk3;
                int c = pk0 ? 0 : (pk1 ? 1 : (pk2 ? 2 : 3));
                float val = pk0 ? cv.x : (pk1 ? cv.y : (pk2 ? cv.z : cv.w));
                bool has = pcnt > 0;
                bool hot = has && (val > HOT_T);
                bool cold = has && !hot;
                unsigned mh = __ballot_sync(0xffffffffu, hot);
                unsigned mc = __ballot_sync(0xffffffffu, cold);
                unsigned mm = __ballot_sync(0xffffffffu, pcnt > 1);
                unsigned below = (1u << lane) - 1u;
                if (has) {
                    unsigned idx = (unsigned)(r - 3) * WW + (unsigned)(colbase + c);
                    unsigned long long key =
                        ((unsigned long long)__float_as_uint(val) << 32) |
                        (unsigned long long)(0xFFFFFFFFu - idx);
                    if (hot) {
                        int slot = nhot + __popc(mh & below);
                        if (slot < SEGCAP) seg[slot] = key;
                    } else {
                        int slot = ncold + __popc(mc & below);
                        if (slot < SEGCAP) seg[SEGCAP - 1 - slot] = key;
                    }
                }
                nhot += __popc(mh);
                ncold += __popc(mc);
                if (mm) {   // tie slow path (exact FP ties only)
                    #pragma unroll
                    for (int cc = 1; cc < 4; cc++) {
                        bool p = (cc == 1 ? pk1 : cc == 2 ? pk2 : pk3) && (cc > c);
                        float v2 = (cc == 1 ? cv.y : cc == 2 ? cv.z : cv.w);
                        bool h2 = p && (v2 > HOT_T);
                        bool c2 = p && !h2;
                        unsigned m2h = __ballot_sync(0xffffffffu, h2);
                        unsigned m2c = __ballot_sync(0xffffffffu, c2);
                        if (p) {
                            unsigned idx = (unsigned)(r - 3) * WW + (unsigned)(colbase + cc);
                            unsigned long long key =
                                ((unsigned long long)__float_as_uint(v2) << 32) |
                                (unsigned long long)(0xFFFFFFFFu - idx);
                            if (h2) {
                                int slot = nhot + __popc(m2h & below);
                                if (slot < SEGCAP) seg[slot] = key;
                            } else {
                                int slot = ncold + __popc(m2c & below);
                                if (slot < SEGCAP) seg[SEGCAP - 1 - slot] = key;
                            }
                        }
                        nhot += __popc(m2h);
                        ncold += __popc(m2c);
                    }
                }
            }
            // rotate pipeline (renamed: inner loop fully unrolled)
            m33 = m32; m32 = m31; m31 = m30; m30 = m3n;
            hp2 = hp1; hp1 = hp0; hp0 = h;

            // issue row i+PIPE into slot (j+8)%12
            {
                int rr = min(max(b0 + i + PIPE, 0), HH - 1);
                const float* rowp = base + (size_t)rr * WW;
                const int js = (j < 4) ? (j + 8) : (j - 4);
                uint32_t s = sbase + (uint32_t)(js * QUADS * 16);
                CP_ASYNC16(s + lane * 16, rowp + c0);
                if (lane2) CP_ASYNC16(s + (32 + lane) * 16, rowp + c1);
                CP_COMMIT();
            }
        }
    }

    if (lane == 0) {
        unsigned nh = nhot > SEGCAP ? SEGCAP : (unsigned)nhot;
        unsigned ncl = ncold > SEGCAP ? SEGCAP : (unsigned)ncold;
        d_segcnt[segid] = nh | (ncl << 16);
    }

    // ---- per-image completion ticket: last block runs the image's top-k ----
    __syncthreads();
    if (threadIdx.x == 0) {
        __threadfence();
        int old = atomicAdd(&d_imgdone[img], 1);
        s_last = (old == BLKS_PER_IMG - 1);
        if (s_last) d_imgdone[img] = 0;     // re-arm for next graph replay
    }
    __syncthreads();
    if (!s_last) return;
    __threadfence();                         // see all blocks' d_seg/d_segcnt

    // ============== tail top-k (128 threads), smem ring reused ==============
    const int tid = threadIdx.x;
    unsigned long long* buf = reinterpret_cast<unsigned long long*>(&ring[0][0][0]);
    unsigned* hist = reinterpret_cast<unsigned*>(buf + SORTN);
    unsigned* scnts = hist + 256;            // 128 segment counts

    const int cbase = img * SEGS_PER_IMG;
    unsigned mycnt = d_segcnt[cbase + tid];  // thread t owns segment t
    scnts[tid] = mycnt;
    int myhot = (int)(mycnt & 0xffffu);

    // exclusive prefix sum of 128 hot counts (warp scan + block combine)
    int x = myhot;
    #pragma unroll
    for (int d = 1; d < 32; d <<= 1) {
        int y = __shfl_up_sync(0xffffffffu, x, d);
        if (lane >= d) x += y;
    }
    if (lane == 31) s_wsum[wid] = x;
    __syncthreads();
    int woff = 0;
    #pragma unroll
    for (int w = 0; w < 4; w++) if (w < wid) woff += s_wsum[w];
    const int mybase = woff + x - myhot;
    const int tot = s_wsum[0] + s_wsum[1] + s_wsum[2] + s_wsum[3];
    __syncthreads();                         // scnts visible; ring no longer live

    if (tot >= TOPK && tot <= SORTN) {
        // ---- fast path: copy hot prefixes (parallel across 128 segments) ----
        const unsigned long long* sp = d_seg + (size_t)(cbase + tid) * SEGCAP;
        for (int i = 0; i < myhot; i++) buf[mybase + i] = sp[i];
        for (int i = tot + tid; i < SORTN; i += 128) buf[i] = 0ull;
    } else {
        // ---- fallback: radix-select over all hot+cold entries (rare) ----
        const int NFLAT = SEGS_PER_IMG * SEGCAP;
        unsigned prefix = 0, above = 0;
        int shift = 24;
        bool done = false;
        for (int lev = 0; lev < 4 && !done; lev++) {
            shift = 24 - lev * 8;
            for (int i = tid; i < 256; i += 128) hist[i] = 0;
            __syncthreads();
            for (int i = tid; i < NFLAT; i += 128) {
                int s = i >> 10, slot = i & (SEGCAP - 1);
                int hh = (int)(scnts[s] & 0xffffu), cc = (int)(scnts[s] >> 16);
                if (slot < hh || slot >= SEGCAP - cc) {
                    unsigned vb = (unsigned)(d_seg[(size_t)(cbase + s) * SEGCAP + slot] >> 32);
                    if (lev == 0 || (vb >> (shift + 8)) == prefix)
                        atomicAdd(&hist[(vb >> shift) & 0xFFu], 1u);
                }
            }
            __syncthreads();
            if (tid == 0) {
                unsigned cum = 0; int dsel = 0;
                for (int b = 255; b >= 0; b--) {
                    if (above + cum + hist[b] >= TOPK || b == 0) { dsel = b; break; }
                    cum += hist[b];
                }
                s_above = above + cum;
                s_digit = (unsigned)dsel;
                s_total = above + cum + hist[dsel];
            }
            __syncthreads();
            above = s_above;
            prefix = (prefix << 8) | s_digit;
            done = (s_total <= SORTN);
            __syncthreads();
        }
        if (tid == 0) s_cnt = 0;
        __syncthreads();
        for (int i = tid; i < NFLAT; i += 128) {
            int s = i >> 10, slot = i & (SEGCAP - 1);
            int hh = (int)(scnts[s] & 0xffffu), cc = (int)(scnts[s] >> 16);
            if (slot < hh || slot >= SEGCAP - cc) {
                unsigned long long k = d_seg[(size_t)(cbase + s) * SEGCAP + slot];
                if (((unsigned)(k >> 32) >> shift) >= prefix) {
                    int pos = atomicAdd(&s_cnt, 1);
                    if (pos < SORTN) buf[pos] = k;
                }
            }
        }
        __syncthreads();
        int m = s_cnt < SORTN ? s_cnt : SORTN;
        for (int i = m + tid; i < SORTN; i += 128) buf[i] = 0ull;
    }
    __syncthreads();

    // bitonic sort of 512 keys with 128 threads (descending)
    for (int k = 2; k <= SORTN; k <<= 1) {
        for (int j = k >> 1; j >= 1; j >>= 1) {
            #pragma unroll
            for (int t = tid; t < SORTN / 2; t += 128) {
                int i0 = ((t / j) * 2 * j) + (t % j);
                int i1 = i0 + j;
                unsigned long long a = buf[i0], b = buf[i1];
                bool takeMax = (i0 & k) == 0;
                if ((a < b) == takeMax) { buf[i0] = b; buf[i1] = a; }
            }
            __syncthreads();
        }
    }

    // emit: coords [B, K, 2] (row, col) then probs [B, K], all fp32
    float* coords = out;
    float* probs = out + (size_t)BATCH * TOPK * 2;
    for (int t = tid; t < TOPK; t += 128) {
        unsigned long long key = buf[t];
        float prob; unsigned row, col;
        if (key == 0ull) {
            prob = 0.0f; row = 0; col = 0;
        } else {
            prob = __uint_as_float((unsigned)(key >> 32));
            unsigned idx = 0xFFFFFFFFu - (unsigned)(key & 0xFFFFFFFFull);
            row = idx / WW; col = idx % WW;
        }
        size_t oo = (size_t)img * TOPK + t;
        coords[oo * 2 + 0] = (float)row;
        coords[oo * 2 + 1] = (float)col;
        probs[oo] = prob;
    }
}

extern "C" void kernel_launch(void* const* d_in, const int* in_sizes, int n_in,
                              void* d_out, int out_size) {
    const float* in = (const float*)d_in[0];
    float* out = (float*)d_out;

    dim3 grid(STRIPS / WPB, NBAND, BATCH);   // 2 x 16 x 32 = 1024 blocks
    nms_kernel<<<grid, 128>>>(in, out);
}

// round 16
// speedup vs baseline: 1.1637x; 1.1637x over previous
#include <cuda_runtime.h>
#include <float.h>
#include <stdint.h>

#define BATCH 32
#define HH 1024
#define WW 1024
#define TOPK 200
#define HOT_T 0.9993f
#define STRIPS 8          // 8 strips x 128 cols
#define CPW 128           // columns per warp
#define WPB 4             // warps per block
#define RPB 64            // rows per band
#define NBAND (HH / RPB)  // 16
#define SEGS_PER_IMG (STRIPS * NBAND)   // 128
#define SEGCAP 1024
#define PIPE 6            // rows in flight
#define RING 10           // smem ring rows (PIPE + 4)
#define QUADS 34          // 136 cols = 128 + 4 halo each side

// static device scratch — per-warp private segments (hot front, cold back)
__device__ unsigned long long d_seg[BATCH * SEGS_PER_IMG * SEGCAP];  // 32 MB
__device__ unsigned int d_segcnt[BATCH * SEGS_PER_IMG];              // hot | cold<<16

__device__ __forceinline__ float4 mk4(float x) { return make_float4(x, x, x, x); }

#define CP_ASYNC16(saddr, gptr)                                                \
    asm volatile("cp.async.cg.shared.global [%0], [%1], 16;\n"                 \
                 :: "r"(saddr), "l"(gptr) : "memory")
#define CP_COMMIT() asm volatile("cp.async.commit_group;\n" ::: "memory")
#define CP_WAIT5()  asm volatile("cp.async.wait_group 5;\n" ::: "memory")

// cp.async-pipelined 7x7 max-pool NMS (R11 structure, smaller ring for
// occupancy). Warp = 128 cols x 64 rows streaming through a 10-row smem ring,
// 6 rows in flight. Bounds via CLAMPED source addressing (a clamped
// out-of-range row/col maps onto a cell already inside the 7x7 window =>
// window max is bit-exact).
__global__ void __launch_bounds__(128) nms_kernel(const float* __restrict__ in) {
    __shared__ float4 ring[WPB][RING][QUADS];    // 21760 B -> 8 blocks/SM

    const int img = blockIdx.z;
    const int wid = threadIdx.x >> 5;
    const int lane = threadIdx.x & 31;
    const int strip = blockIdx.x * WPB + wid;    // 0..7
    const int band = blockIdx.y;                 // 0..15
    const int out0 = strip * CPW;
    const int colbase = out0 + 4 * lane;
    const int ry0 = band * RPB;
    const int b0 = ry0 - 3;
    const float* base = in + (size_t)img * HH * WW;

    const int segid = (img * NBAND + band) * STRIPS + strip;
    unsigned long long* seg = d_seg + (size_t)segid * SEGCAP;
    int nhot = 0, ncold = 0;

    // clamped source columns for this lane's quads
    int c0 = out0 - 4 + 4 * lane;                // quads 0..31
    c0 = min(max(c0, 0), WW - 4);
    int c1 = out0 + 124 + 4 * lane;              // quads 32,33 (lanes 0,1)
    c1 = min(c1, WW - 4);
    const bool lane2 = lane < 2;

    const uint32_t sbase =
        (uint32_t)__cvta_generic_to_shared(&ring[wid][0][0]);

    // prologue: issue rows 0..PIPE-1 into slots 0..PIPE-1
    #pragma unroll
    for (int i = 0; i < PIPE; i++) {
        int rr = min(max(b0 + i, 0), HH - 1);
        const float* rowp = base + (size_t)rr * WW;
        uint32_t s = sbase + (uint32_t)(i * QUADS * 16);
        CP_ASYNC16(s + lane * 16, rowp + c0);
        if (lane2) CP_ASYNC16(s + (32 + lane) * 16, rowp + c1);
        CP_COMMIT();
    }

    // rolling vertical state: h[r-1..r-3], m3 centered r-2..r-5
    float4 hp0 = mk4(-FLT_MAX), hp1 = hp0, hp2 = hp0;
    float4 m30 = hp0, m31 = hp0, m32 = hp0, m33 = hp0;

    for (int o = 0; o < 7; o++) {                // 70 rows: b0 .. b0+69 exactly
        #pragma unroll
        for (int j = 0; j < RING; j++) {
            const int i = o * RING + j;
            const int r = b0 + i;
            CP_WAIT5();
            __syncwarp();

            const float4* rb = &ring[wid][j][0];
            float4 L = rb[lane];
            float4 O = rb[lane + 1];
            float4 R = rb[lane + 2];

            // horizontal 7-max from L/O/R quads
            float p3 = fmaxf(fmaxf(O.x, O.y), fmaxf(O.z, O.w));
            float Lzw = fmaxf(L.z, L.w);
            float Ls3 = fmaxf(L.y, Lzw);
            float Rxy = fmaxf(R.x, R.y);
            float4 h;
            h.x = fmaxf(Ls3, p3);
            h.y = fmaxf(Lzw, fmaxf(p3, R.x));
            h.z = fmaxf(L.w, fmaxf(p3, Rxy));
            h.w = fmaxf(p3, fmaxf(Rxy, R.z));

            // vertical cascade
            float4 m3n, pooled;
            m3n.x = fmaxf(fmaxf(hp1.x, hp0.x), h.x);
            m3n.y = fmaxf(fmaxf(hp1.y, hp0.y), h.y);
            m3n.z = fmaxf(fmaxf(hp1.z, hp0.z), h.z);
            m3n.w = fmaxf(fmaxf(hp1.w, hp0.w), h.w);
            pooled.x = fmaxf(fmaxf(m33.x, hp2.x), m3n.x);
            pooled.y = fmaxf(fmaxf(m33.y, hp2.y), m3n.y);
            pooled.z = fmaxf(fmaxf(m33.z, hp2.z), m3n.z);
            pooled.w = fmaxf(fmaxf(m33.w, hp2.w), m3n.w);

            if (r >= ry0 + 3 && r <= ry0 + RPB + 2) {
                // center row r-3 from the ring (own quad); slot (j-3) mod 10
                const int jc = (j >= 3) ? (j - 3) : (j + 7);
                float4 cv = ring[wid][jc][lane + 1];

                bool pk0 = (cv.x > 0.1f) && (pooled.x == cv.x);
                bool pk1 = (cv.y > 0.1f) && (pooled.y == cv.y);
                bool pk2 = (cv.z > 0.1f) && (pooled.z == cv.z);
                bool pk3 = (cv.w > 0.1f) && (pooled.w == cv.w);
                int pcnt = (int)pk0 + (int)pk1 + (int)pk2 + (int)pk3;
                int c = pk0 ? 0 : (pk1 ? 1 : (pk2 ? 2 : 3));
                float val = pk0 ? cv.x : (pk1 ? cv.y : (pk2 ? cv.z : cv.w));
                bool has = pcnt > 0;
                bool hot = has && (val > HOT_T);
                bool cold = has && !hot;
                unsigned mh = __ballot_sync(0xffffffffu, hot);
                unsigned mc = __ballot_sync(0xffffffffu, cold);
                unsigned mm = __ballot_sync(0xffffffffu, pcnt > 1);
                unsigned below = (1u << lane) - 1u;
                if (has) {
                    unsigned idx = (unsigned)(r - 3) * WW + (unsigned)(colbase + c);
                    unsigned long long key =
                        ((unsigned long long)__float_as_uint(val) << 32) |
                        (unsigned long long)(0xFFFFFFFFu - idx);
                    if (hot) {
                        int slot = nhot + __popc(mh & below);
                        if (slot < SEGCAP) seg[slot] = key;
                    } else {
                        int slot = ncold + __popc(mc & below);
                        if (slot < SEGCAP) seg[SEGCAP - 1 - slot] = key;
                    }
                }
                nhot += __popc(mh);
                ncold += __popc(mc);
                if (mm) {   // tie slow path (exact FP ties only)
                    #pragma unroll
                    for (int cc = 1; cc < 4; cc++) {
                        bool p = (cc == 1 ? pk1 : cc == 2 ? pk2 : pk3) && (cc > c);
                        float v2 = (cc == 1 ? cv.y : cc == 2 ? cv.z : cv.w);
                        bool h2 = p && (v2 > HOT_T);
                        bool c2 = p && !h2;
                        unsigned m2h = __ballot_sync(0xffffffffu, h2);
                        unsigned m2c = __ballot_sync(0xffffffffu, c2);
                        if (p) {
                            unsigned idx = (unsigned)(r - 3) * WW + (unsigned)(colbase + cc);
                            unsigned long long key =
                                ((unsigned long long)__float_as_uint(v2) << 32) |
                                (unsigned long long)(0xFFFFFFFFu - idx);
                            if (h2) {
                                int slot = nhot + __popc(m2h & below);
                                if (slot < SEGCAP) seg[slot] = key;
                            } else {
                                int slot = ncold + __popc(m2c & below);
                                if (slot < SEGCAP) seg[SEGCAP - 1 - slot] = key;
                            }
                        }
                        nhot += __popc(m2h);
                        ncold += __popc(m2c);
                    }
                }
            }
            // rotate pipeline (renamed: inner loop fully unrolled)
            m33 = m32; m32 = m31; m31 = m30; m30 = m3n;
            hp2 = hp1; hp1 = hp0; hp0 = h;

            // issue row i+PIPE into slot (j+6)%10 (it held row i-4: aged out)
            {
                int rr = min(max(b0 + i + PIPE, 0), HH - 1);
                const float* rowp = base + (size_t)rr * WW;
                const int js = (j < 4) ? (j + 6) : (j - 4);
                uint32_t s = sbase + (uint32_t)(js * QUADS * 16);
                CP_ASYNC16(s + lane * 16, rowp + c0);
                if (lane2) CP_ASYNC16(s + (32 + lane) * 16, rowp + c1);
                CP_COMMIT();
            }
        }
    }

    if (lane == 0) {
        unsigned nh = nhot > SEGCAP ? SEGCAP : (unsigned)nhot;
        unsigned ncl = ncold > SEGCAP ? SEGCAP : (unsigned)ncold;
        d_segcnt[segid] = nh | (ncl << 16);
    }
}

// One block per image. Gather hot keys, hybrid register/shared bitonic sort.
__global__ void __launch_bounds__(1024) topk_kernel(float* __restrict__ out) {
    const int img = blockIdx.x;
    const int tid = threadIdx.x;
    const int lane = tid & 31;
    const int wrp = tid >> 5;

    __shared__ unsigned long long buf[1024];
    __shared__ int s_cnt;
    __shared__ unsigned scnt[SEGS_PER_IMG];
    __shared__ unsigned hist[256];
    __shared__ unsigned s_above, s_digit, s_total;

    const int cbase = img * SEGS_PER_IMG;
    for (int i = tid; i < SEGS_PER_IMG; i += 1024)
        scnt[i] = d_segcnt[cbase + i];
    if (tid == 0) s_cnt = 0;
    __syncthreads();

    // gather hot prefixes (warp per segment)
    for (int s = wrp; s < SEGS_PER_IMG; s += 32) {
        int hot = (int)(scnt[s] & 0xffffu);
        const unsigned long long* seg = d_seg + (size_t)(cbase + s) * SEGCAP;
        for (int i0 = 0; i0 < hot; i0 += 32) {
            int i = i0 + lane;
            bool vld = i < hot;
            unsigned m = __ballot_sync(0xffffffffu, vld);
            int bs = 0;
            if (lane == 0) bs = atomicAdd(&s_cnt, __popc(m));
            bs = __shfl_sync(0xffffffffu, bs, 0);
            if (vld) {
                int pos = bs + __popc(m & ((1u << lane) - 1u));
                if (pos < 1024) buf[pos] = seg[i];
            }
        }
    }
    __syncthreads();
    int nhot = s_cnt;

    if (nhot >= TOPK && nhot <= 1024) {
        if (tid >= nhot) buf[tid] = 0ull;
    } else {
        // ---- fallback: radix-select over all hot+cold entries ----
        const int NFLAT = SEGS_PER_IMG * SEGCAP;
        unsigned prefix = 0, above = 0;
        int shift = 24;
        bool done = false;
        for (int lev = 0; lev < 4 && !done; lev++) {
            shift = 24 - lev * 8;
            for (int i = tid; i < 256; i += 1024) hist[i] = 0;
            __syncthreads();
            for (int i = tid; i < NFLAT; i += 1024) {
                int s = i >> 10, slot = i & (SEGCAP - 1);
                int h = (int)(scnt[s] & 0xffffu), c = (int)(scnt[s] >> 16);
                if (slot < h || slot >= SEGCAP - c) {
                    unsigned vb = (unsigned)(d_seg[(size_t)(cbase + s) * SEGCAP + slot] >> 32);
                    if (lev == 0 || (vb >> (shift + 8)) == prefix)
                        atomicAdd(&hist[(vb >> shift) & 0xFFu], 1u);
                }
            }
            __syncthreads();
            if (tid == 0) {
                unsigned cum = 0; int dsel = 0;
                for (int b = 255; b >= 0; b--) {
                    if (above + cum + hist[b] >= TOPK || b == 0) { dsel = b; break; }
                    cum += hist[b];
                }
                s_above = above + cum;
                s_digit = (unsigned)dsel;
                s_total = above + cum + hist[dsel];
            }
            __syncthreads();
            above = s_above;
            prefix = (prefix << 8) | s_digit;
            done = (s_total <= 1024);
            __syncthreads();
        }
        if (tid == 0) s_cnt = 0;
        __syncthreads();
        for (int i = tid; i < NFLAT; i += 1024) {
            int s = i >> 10, slot = i & (SEGCAP - 1);
            int h = (int)(scnt[s] & 0xffffu), c = (int)(scnt[s] >> 16);
            if (slot < h || slot >= SEGCAP - c) {
                unsigned long long k = d_seg[(size_t)(cbase + s) * SEGCAP + slot];
                if (((unsigned)(k >> 32) >> shift) >= prefix) {
                    int pos = atomicAdd(&s_cnt, 1);
                    if (pos < 1024) buf[pos] = k;
                }
            }
        }
        __syncthreads();
        int m = s_cnt < 1024 ? s_cnt : 1024;
        if (tid >= m) buf[tid] = 0ull;
    }
    __syncthreads();

    // hybrid bitonic sort, descending: j>=32 via shared, j<32 via shfl_xor
    unsigned long long key = buf[tid];
    #pragma unroll
    for (int k = 2; k <= 1024; k <<= 1) {
        #pragma unroll
        for (int j = k >> 1; j >= 32; j >>= 1) {
            buf[tid] = key;
            __syncthreads();
            unsigned long long other = buf[tid ^ j];
            __syncthreads();
            bool takeMax = (((tid & k) == 0) == ((tid & j) == 0));
            key = (takeMax == (key > other)) ? key : other;
        }
        #pragma unroll
        for (int j = (k >> 1) < 16 ? (k >> 1) : 16; j >= 1; j >>= 1) {
            unsigned long long other = __shfl_xor_sync(0xffffffffu, key, j);
            bool takeMax = (((tid & k) == 0) == ((tid & j) == 0));
            key = (takeMax == (key > other)) ? key : other;
        }
    }

    // emit: coords [B, K, 2] (row, col) then probs [B, K], all fp32
    float* coords = out;
    float* probs = out + (size_t)BATCH * TOPK * 2;
    if (tid < TOPK) {
        float prob; unsigned row, col;
        if (key == 0ull) {
            prob = 0.0f; row = 0; col = 0;
        } else {
            prob = __uint_as_float((unsigned)(key >> 32));
            unsigned idx = 0xFFFFFFFFu - (unsigned)(key & 0xFFFFFFFFull);
            row = idx / WW; col = idx % WW;
        }
        size_t o = (size_t)img * TOPK + tid;
        coords[o * 2 + 0] = (float)row;
        coords[o * 2 + 1] = (float)col;
        probs[o] = prob;
    }
}

extern "C" void kernel_launch(void* const* d_in, const int* in_sizes, int n_in,
                              void* d_out, int out_size) {
    const float* in = (const float*)d_in[0];
    float* out = (float*)d_out;

    // grant the full smem pool so 8 blocks/SM fit (idempotent, capture-safe)
    cudaFuncSetAttribute(nms_kernel,
                         cudaFuncAttributePreferredSharedMemoryCarveout, 100);

    dim3 grid(STRIPS / WPB, NBAND, BATCH);   // 2 x 16 x 32 = 1024 blocks
    nms_kernel<<<grid, 128>>>(in);
    topk_kernel<<<BATCH, 1024>>>(out);
}

// round 17
// speedup vs baseline: 1.3398x; 1.1513x over previous
#include <cuda_runtime.h>
#include <float.h>
#include <stdint.h>

#define BATCH 32
#define HH 1024
#define WW 1024
#define TOPK 200
#define HOT_T 0.9993f
#define STRIPS 8          // 8 strips x 128 cols
#define CPW 128           // columns per warp
#define WPB 4             // warps per block
#define RPB 64            // rows per band
#define NBAND (HH / RPB)  // 16
#define SEGS_PER_IMG (STRIPS * NBAND)   // 128
#define SEGCAP 64         // hot keys per 128x64 tile: E~5.6, cap 64
#define PIPE 6            // rows in flight
#define RING 10           // smem ring rows (PIPE + 4)
#define QUADS 34          // 136 cols = 128 + 4 halo each side

// static device scratch — per-warp hot-only segments
__device__ unsigned long long d_seg[BATCH * SEGS_PER_IMG * SEGCAP];  // 2 MB
__device__ int d_segcnt[BATCH * SEGS_PER_IMG];                       // raw hot count

__device__ __forceinline__ float4 mk4(float x) { return make_float4(x, x, x, x); }

#define CP_ASYNC16(saddr, gptr)                                                \
    asm volatile("cp.async.cg.shared.global [%0], [%1], 16;\n"                 \
                 :: "r"(saddr), "l"(gptr) : "memory")
#define CP_COMMIT() asm volatile("cp.async.commit_group;\n" ::: "memory")
#define CP_WAIT5()  asm volatile("cp.async.wait_group 5;\n" ::: "memory")

// cp.async-pipelined 7x7 max-pool NMS (R16 structure), HOT-ONLY emission:
// only peaks with value > HOT_T are recorded (single ballot + front write).
// Peaks in (0.1, HOT_T] are recovered by topk's brute-force fallback, which
// never triggers when >= TOPK hot peaks exist (then top-K are all hot).
// Bounds via CLAMPED source addressing (a clamped out-of-range row/col maps
// onto a cell already inside the 7x7 window => window max is bit-exact).
__global__ void __launch_bounds__(128) nms_kernel(const float* __restrict__ in) {
    __shared__ float4 ring[WPB][RING][QUADS];    // 21760 B

    const int img = blockIdx.z;
    const int wid = threadIdx.x >> 5;
    const int lane = threadIdx.x & 31;
    const int strip = blockIdx.x * WPB + wid;    // 0..7
    const int band = blockIdx.y;                 // 0..15
    const int out0 = strip * CPW;
    const int colbase = out0 + 4 * lane;
    const int ry0 = band * RPB;
    const int b0 = ry0 - 3;
    const float* base = in + (size_t)img * HH * WW;

    const int segid = (img * NBAND + band) * STRIPS + strip;
    unsigned long long* seg = d_seg + (size_t)segid * SEGCAP;
    int nhot = 0;

    // clamped source columns for this lane's quads
    int c0 = out0 - 4 + 4 * lane;                // quads 0..31
    c0 = min(max(c0, 0), WW - 4);
    int c1 = out0 + 124 + 4 * lane;              // quads 32,33 (lanes 0,1)
    c1 = min(c1, WW - 4);
    const bool lane2 = lane < 2;

    const uint32_t sbase =
        (uint32_t)__cvta_generic_to_shared(&ring[wid][0][0]);

    // prologue: issue rows 0..PIPE-1 into slots 0..PIPE-1
    #pragma unroll
    for (int i = 0; i < PIPE; i++) {
        int rr = min(max(b0 + i, 0), HH - 1);
        const float* rowp = base + (size_t)rr * WW;
        uint32_t s = sbase + (uint32_t)(i * QUADS * 16);
        CP_ASYNC16(s + lane * 16, rowp + c0);
        if (lane2) CP_ASYNC16(s + (32 + lane) * 16, rowp + c1);
        CP_COMMIT();
    }

    // rolling vertical state: h[r-1..r-3], m3 centered r-2..r-5
    float4 hp0 = mk4(-FLT_MAX), hp1 = hp0, hp2 = hp0;
    float4 m30 = hp0, m31 = hp0, m32 = hp0, m33 = hp0;

    for (int o = 0; o < 7; o++) {                // 70 rows: b0 .. b0+69 exactly
        #pragma unroll
        for (int j = 0; j < RING; j++) {
            const int i = o * RING + j;
            const int r = b0 + i;
            CP_WAIT5();
            __syncwarp();

            const float4* rb = &ring[wid][j][0];
            float4 L = rb[lane];
            float4 O = rb[lane + 1];
            float4 R = rb[lane + 2];

            // horizontal 7-max from L/O/R quads
            float p3 = fmaxf(fmaxf(O.x, O.y), fmaxf(O.z, O.w));
            float Lzw = fmaxf(L.z, L.w);
            float Ls3 = fmaxf(L.y, Lzw);
            float Rxy = fmaxf(R.x, R.y);
            float4 h;
            h.x = fmaxf(Ls3, p3);
            h.y = fmaxf(Lzw, fmaxf(p3, R.x));
            h.z = fmaxf(L.w, fmaxf(p3, Rxy));
            h.w = fmaxf(p3, fmaxf(Rxy, R.z));

            // vertical cascade
            float4 m3n, pooled;
            m3n.x = fmaxf(fmaxf(hp1.x, hp0.x), h.x);
            m3n.y = fmaxf(fmaxf(hp1.y, hp0.y), h.y);
            m3n.z = fmaxf(fmaxf(hp1.z, hp0.z), h.z);
            m3n.w = fmaxf(fmaxf(hp1.w, hp0.w), h.w);
            pooled.x = fmaxf(fmaxf(m33.x, hp2.x), m3n.x);
            pooled.y = fmaxf(fmaxf(m33.y, hp2.y), m3n.y);
            pooled.z = fmaxf(fmaxf(m33.z, hp2.z), m3n.z);
            pooled.w = fmaxf(fmaxf(m33.w, hp2.w), m3n.w);

            if (r >= ry0 + 3 && r <= ry0 + RPB + 2) {
                // center row r-3 from the ring (own quad); slot (j-3) mod 10
                const int jc = (j >= 3) ? (j - 3) : (j + 7);
                float4 cv = ring[wid][jc][lane + 1];

                // hot peaks only (> HOT_T subsumes > 0.1)
                bool h0 = (cv.x > HOT_T) && (pooled.x == cv.x);
                bool h1 = (cv.y > HOT_T) && (pooled.y == cv.y);
                bool h2 = (cv.z > HOT_T) && (pooled.z == cv.z);
                bool h3 = (cv.w > HOT_T) && (pooled.w == cv.w);
                int hcnt = (int)h0 + (int)h1 + (int)h2 + (int)h3;
                int c = h0 ? 0 : (h1 ? 1 : (h2 ? 2 : 3));
                float val = h0 ? cv.x : (h1 ? cv.y : (h2 ? cv.z : cv.w));
                bool has = hcnt > 0;
                unsigned mh = __ballot_sync(0xffffffffu, has);
                unsigned mm = __ballot_sync(0xffffffffu, hcnt > 1);
                unsigned below = (1u << lane) - 1u;
                if (has) {
                    unsigned idx = (unsigned)(r - 3) * WW + (unsigned)(colbase + c);
                    unsigned long long key =
                        ((unsigned long long)__float_as_uint(val) << 32) |
                        (unsigned long long)(0xFFFFFFFFu - idx);
                    int slot = nhot + __popc(mh & below);
                    if (slot < SEGCAP) seg[slot] = key;
                }
                nhot += __popc(mh);
                if (mm) {   // >1 hot peak in a quad: exact FP ties only
                    #pragma unroll
                    for (int cc = 1; cc < 4; cc++) {
                        bool p = (cc == 1 ? h1 : cc == 2 ? h2 : h3) && (cc > c);
                        unsigned m2 = __ballot_sync(0xffffffffu, p);
                        if (p) {
                            float v2 = (cc == 1 ? cv.y : cc == 2 ? cv.z : cv.w);
                            unsigned idx = (unsigned)(r - 3) * WW + (unsigned)(colbase + cc);
                            unsigned long long key =
                                ((unsigned long long)__float_as_uint(v2) << 32) |
                                (unsigned long long)(0xFFFFFFFFu - idx);
                            int slot = nhot + __popc(m2 & below);
                            if (slot < SEGCAP) seg[slot] = key;
                        }
                        nhot += __popc(m2);
                    }
                }
            }
            // rotate pipeline (renamed: inner loop fully unrolled)
            m33 = m32; m32 = m31; m31 = m30; m30 = m3n;
            hp2 = hp1; hp1 = hp0; hp0 = h;

            // issue row i+PIPE into slot (j+6)%10
            {
                int rr = min(max(b0 + i + PIPE, 0), HH - 1);
                const float* rowp = base + (size_t)rr * WW;
                const int js = (j < 4) ? (j + 6) : (j - 4);
                uint32_t s = sbase + (uint32_t)(js * QUADS * 16);
                CP_ASYNC16(s + lane * 16, rowp + c0);
                if (lane2) CP_ASYNC16(s + (32 + lane) * 16, rowp + c1);
                CP_COMMIT();
            }
        }
    }

    if (lane == 0) d_segcnt[segid] = nhot;   // raw (overflow detectable)
}

// One block per image. Fast path: gather hot keys, hybrid bitonic sort.
// Fallback (hot count out of range or segment overflow — off-distribution
// only): brute-force radix-select recomputing the 7x7 NMS from the input.
__global__ void __launch_bounds__(1024) topk_kernel(const float* __restrict__ in,
                                                    float* __restrict__ out) {
    const int img = blockIdx.x;
    const int tid = threadIdx.x;
    const int lane = tid & 31;
    const int wrp = tid >> 5;

    __shared__ unsigned long long buf[1024];
    __shared__ int s_cnt;
    __shared__ int s_bad;
    __shared__ int scnt[SEGS_PER_IMG];
    __shared__ unsigned hist[256];
    __shared__ unsigned s_above, s_digit, s_total;

    const int cbase = img * SEGS_PER_IMG;
    if (tid == 0) { s_cnt = 0; s_bad = 0; }
    __syncthreads();
    for (int i = tid; i < SEGS_PER_IMG; i += 1024) {
        int c = d_segcnt[cbase + i];
        scnt[i] = c;
        if (c > SEGCAP) s_bad = 1;
    }
    __syncthreads();

    // gather hot keys (warp per segment)
    if (!s_bad) {
        for (int s = wrp; s < SEGS_PER_IMG; s += 32) {
            int hot = scnt[s];
            const unsigned long long* seg = d_seg + (size_t)(cbase + s) * SEGCAP;
            for (int i0 = 0; i0 < hot; i0 += 32) {
                int i = i0 + lane;
                bool vld = i < hot;
                unsigned m = __ballot_sync(0xffffffffu, vld);
                int bs = 0;
                if (lane == 0) bs = atomicAdd(&s_cnt, __popc(m));
                bs = __shfl_sync(0xffffffffu, bs, 0);
                if (vld) {
                    int pos = bs + __popc(m & ((1u << lane) - 1u));
                    if (pos < 1024) buf[pos] = seg[i];
                }
            }
        }
    }
    __syncthreads();
    int nhot = s_cnt;

    if (!s_bad && nhot >= TOPK && nhot <= 1024) {
        if (tid >= nhot) buf[tid] = 0ull;
    } else {
        // ---- fallback: brute-force radix-select, recomputing NMS ----
        const float* base = in + (size_t)img * HH * WW;
        unsigned prefix = 0, above = 0;
        int shift = 24;
        bool done = false;
        for (int lev = 0; lev < 4 && !done; lev++) {
            shift = 24 - lev * 8;
            for (int i = tid; i < 256; i += 1024) hist[i] = 0;
            __syncthreads();
            for (int i = tid; i < HH * WW; i += 1024) {
                int row = i >> 10, col = i & (WW - 1);
                float center = base[i];
                if (center > 0.1f) {
                    float mx = -FLT_MAX;
                    for (int dr = -3; dr <= 3; dr++) {
                        int rr = row + dr;
                        if ((unsigned)rr < HH)
                            for (int dc = -3; dc <= 3; dc++) {
                                int cc = col + dc;
                                if ((unsigned)cc < WW)
                                    mx = fmaxf(mx, base[(size_t)rr * WW + cc]);
                            }
                    }
                    if (mx == center) {
                        unsigned vb = __float_as_uint(center);
                        if (lev == 0 || (vb >> (shift + 8)) == prefix)
                            atomicAdd(&hist[(vb >> shift) & 0xFFu], 1u);
                    }
                }
            }
            __syncthreads();
            if (tid == 0) {
                unsigned cum = 0; int dsel = 0;
                for (int b = 255; b >= 0; b--) {
                    if (above + cum + hist[b] >= TOPK || b == 0) { dsel = b; break; }
                    cum += hist[b];
                }
                s_above = above + cum;
                s_digit = (unsigned)dsel;
                s_total = above + cum + hist[dsel];
            }
            __syncthreads();
            above = s_above;
            prefix = (prefix << 8) | s_digit;
            done = (s_total <= 1024);
            __syncthreads();
        }
        if (tid == 0) s_cnt = 0;
        __syncthreads();
        for (int i = tid; i < HH * WW; i += 1024) {
            int row = i >> 10, col = i & (WW - 1);
            float center = base[i];
            if (center > 0.1f) {
                float mx = -FLT_MAX;
                for (int dr = -3; dr <= 3; dr++) {
                    int rr = row + dr;
                    if ((unsigned)rr < HH)
                        for (int dc = -3; dc <= 3; dc++) {
                            int cc = col + dc;
                            if ((unsigned)cc < WW)
                                mx = fmaxf(mx, base[(size_t)rr * WW + cc]);
                        }
                }
                if (mx == center) {
                    unsigned vb = __float_as_uint(center);
                    if ((vb >> shift) >= prefix) {
                        unsigned long long key =
                            ((unsigned long long)vb << 32) |
                            (unsigned long long)(0xFFFFFFFFu - (unsigned)i);
                        int pos = atomicAdd(&s_cnt, 1);
                        if (pos < 1024) buf[pos] = key;
                    }
                }
            }
        }
        __syncthreads();
        int m = s_cnt < 1024 ? s_cnt : 1024;
        if (tid >= m) buf[tid] = 0ull;
    }
    __syncthreads();

    // hybrid bitonic sort, descending: j>=32 via shared, j<32 via shfl_xor
    unsigned long long key = buf[tid];
    #pragma unroll
    for (int k = 2; k <= 1024; k <<= 1) {
        #pragma unroll
        for (int j = k >> 1; j >= 32; j >>= 1) {
            buf[tid] = key;
            __syncthreads();
            unsigned long long other = buf[tid ^ j];
            __syncthreads();
            bool takeMax = (((tid & k) == 0) == ((tid & j) == 0));
            key = (takeMax == (key > other)) ? key : other;
        }
        #pragma unroll
        for (int j = (k >> 1) < 16 ? (k >> 1) : 16; j >= 1; j >>= 1) {
            unsigned long long other = __shfl_xor_sync(0xffffffffu, key, j);
            bool takeMax = (((tid & k) == 0) == ((tid & j) == 0));
            key = (takeMax == (key > other)) ? key : other;
        }
    }

    // emit: coords [B, K, 2] (row, col) then probs [B, K], all fp32
    float* coords = out;
    float* probs = out + (size_t)BATCH * TOPK * 2;
    if (tid < TOPK) {
        float prob; unsigned row, col;
        if (key == 0ull) {
            prob = 0.0f; row = 0; col = 0;
        } else {
            prob = __uint_as_float((unsigned)(key >> 32));
            unsigned idx = 0xFFFFFFFFu - (unsigned)(key & 0xFFFFFFFFull);
            row = idx / WW; col = idx % WW;
        }
        size_t o = (size_t)img * TOPK + tid;
        coords[o * 2 + 0] = (float)row;
        coords[o * 2 + 1] = (float)col;
        probs[o] = prob;
    }
}

extern "C" void kernel_launch(void* const* d_in, const int* in_sizes, int n_in,
                              void* d_out, int out_size) {
    const float* in = (const float*)d_in[0];
    float* out = (float*)d_out;

    cudaFuncSetAttribute(nms_kernel,
                         cudaFuncAttributePreferredSharedMemoryCarveout, 100);

    dim3 grid(STRIPS / WPB, NBAND, BATCH);   // 2 x 16 x 32 = 1024 blocks
    nms_kernel<<<grid, 128>>>(in);
    topk_kernel<<<BATCH, 1024>>>(in, out);
}